// round 3
// baseline (speedup 1.0000x reference)
#include <cuda_runtime.h>
#include <math.h>

// Problem constants (fixed shapes from reference)
#define HEADS_N 4
#define BSZ 2
#define NTOT 8192        // THW
#define MTOT 1024        // HW
#define CKTOT 64
#define CVTOT 512
#define M_T 64           // m-tile per block
#define NSPLIT 4
#define NPS (NTOT / NSPLIT)   // 2048 n per split
#define NC 32            // n chunk staged in smem
#define NTHREADS 512

// Partial accumulators: [split][b][cv][m]  (16 MB static scratch; no cudaMalloc)
__device__ __align__(16) float g_partial[NSPLIT * BSZ * CVTOT * MTOT];

// ---------- packed f32x2 helpers (FFMA2 — sm_100+ only, ptxas never auto-fuses) ----
typedef unsigned long long u64;
__device__ __forceinline__ u64 pk2(float lo, float hi) {
    u64 r; asm("mov.b64 %0,{%1,%2};" : "=l"(r) : "f"(lo), "f"(hi)); return r;
}
__device__ __forceinline__ void up2(u64 v, float& lo, float& hi) {
    asm("mov.b64 {%0,%1},%2;" : "=f"(lo), "=f"(hi) : "l"(v));
}
__device__ __forceinline__ void fma2(u64& d, u64 a, u64 b) {
    asm("fma.rn.f32x2 %0,%1,%2,%0;" : "+l"(d) : "l"(a), "l"(b));
}

struct SmemLayout {
    float Qs[HEADS_N][32][M_T];        // rows: k<16 -> -qe ; k>=16 -> 2*qk*qe   (32 KB)
    float Kt[HEADS_N][32][NC + 2];     // rows: k<16 -> mk^3 ; k>=16 -> mk (stride 34, LDS.64-aligned)
    float Ps[HEADS_N][NC][M_T + 1];    // scores->probs, layout [h][n][m], stride 65
    float mvs[NC][CVTOT + 2];          // mv TRANSPOSED: [nn][cv], stride 514 (LDS.64-aligned)
    float bias[HEADS_N][M_T];          // b_sq = sum_c qe*qk^3
    float mss[NC];                     // ms for this n chunk
};

__global__ void __launch_bounds__(NTHREADS, 1)
mem_reader_kernel(const float* __restrict__ mk, const float* __restrict__ qk,
                  const float* __restrict__ ms, const float* __restrict__ qe,
                  const float* __restrict__ mv)
{
    extern __shared__ float smem_raw[];
    SmemLayout* sm = reinterpret_cast<SmemLayout*>(smem_raw);

    const int tid   = threadIdx.x;
    const int bx    = blockIdx.x;          // 128 blocks total
    const int split = bx & 3;
    const int mtile = (bx >> 2) & 15;
    const int b     = bx >> 6;
    const int m0    = mtile * M_T;
    const int nbase = split * NPS;

    // ---- Block setup: query-side smem (Qs) and bias ----
    for (int i = tid; i < CKTOT * M_T; i += NTHREADS) {
        int row = i >> 6;            // h*16+c
        int ml  = i & 63;
        int h = row >> 4, c = row & 15;
        float qe_v = qe[(size_t)(b * CKTOT + row) * MTOT + m0 + ml];
        float qk_v = qk[(size_t)(b * CKTOT + row) * MTOT + m0 + ml];
        sm->Qs[h][c][ml]      = -qe_v;
        sm->Qs[h][16 + c][ml] = 2.0f * qk_v * qe_v;
    }
    if (tid < HEADS_N * M_T) {
        int h = tid >> 6, ml = tid & 63;
        float s = 0.0f;
        #pragma unroll
        for (int c = 0; c < 16; c++) {
            float qe_v = qe[(size_t)(b * CKTOT + h * 16 + c) * MTOT + m0 + ml];
            float qk_v = qk[(size_t)(b * CKTOT + h * 16 + c) * MTOT + m0 + ml];
            s += qe_v * qk_v * qk_v * qk_v;
        }
        sm->bias[h][ml] = s;
    }

    // ---- Phase B thread mapping: 64 cv-groups x 8 m-groups ----
    const int cvg = tid >> 3;        // 0..63 -> cv0 = cvg*8
    const int mg  = tid & 7;         // m_local = mg + 8*jm
    const int hB  = cvg >> 4;        // head for readout

    // ---- Phase A thread mapping: (h, 4n, 4m) per thread ----
    const int hA  = tid >> 7;        // 0..3
    const int nq4 = ((tid >> 4) & 7) * 4;
    const int mq4 = (tid & 15) * 4;

    // Phase B accumulators: lanes = (cv even, cv odd) pair. [jcp][jm]
    u64 acc2[4][8];
    #pragma unroll
    for (int a = 0; a < 4; a++)
        #pragma unroll
        for (int j = 0; j < 8; j++) acc2[a][j] = 0ull;

    __syncthreads();

    const float inv_sqrt_ck = 0.125f;   // 1/sqrt(64)

    for (int chunk = 0; chunk < NPS / NC; chunk++) {
        const int n0 = nbase + chunk * NC;

        // ---- Stage key-side tile: mk and mk^3 (coalesced along n) ----
        for (int i = tid; i < CKTOT * NC; i += NTHREADS) {
            int row = i >> 5;        // h*16+c
            int nn  = i & 31;
            float v = mk[(size_t)(b * CKTOT + row) * NTOT + n0 + nn];
            int h = row >> 4, c = row & 15;
            sm->Kt[h][c][nn]      = v * v * v;
            sm->Kt[h][16 + c][nn] = v;
        }
        // ---- Stage mv tile TRANSPOSED to [nn][cv] (gmem reads stay coalesced) ----
        for (int i = tid; i < CVTOT * NC; i += NTHREADS) {
            int row = i >> 5, nn = i & 31;
            sm->mvs[nn][row] = mv[(size_t)(b * CVTOT + row) * NTOT + n0 + nn];
        }
        if (tid < NC) sm->mss[tid] = ms[(size_t)b * NTOT + n0 + tid];
        __syncthreads();

        // ---- Phase A: raw scores; lanes = n pair. a2[p][j], p: n pair, j: m ----
        {
            u64 a2[2][4];
            #pragma unroll
            for (int p = 0; p < 2; p++)
                #pragma unroll
                for (int j = 0; j < 4; j++) a2[p][j] = 0ull;

            #pragma unroll 8
            for (int k = 0; k < 32; k++) {
                float2 kf0 = *reinterpret_cast<const float2*>(&sm->Kt[hA][k][nq4]);
                float2 kf1 = *reinterpret_cast<const float2*>(&sm->Kt[hA][k][nq4 + 2]);
                u64 kv0 = pk2(kf0.x, kf0.y);
                u64 kv1 = pk2(kf1.x, kf1.y);
                #pragma unroll
                for (int j = 0; j < 4; j++) {
                    float q = sm->Qs[hA][k][mq4 + j];
                    u64 qb = pk2(q, q);
                    fma2(a2[0][j], kv0, qb);
                    fma2(a2[1][j], kv1, qb);
                }
            }
            #pragma unroll
            for (int j = 0; j < 4; j++) {
                float bj = sm->bias[hA][mq4 + j];
                #pragma unroll
                for (int p = 0; p < 2; p++) {
                    float s0, s1;
                    up2(a2[p][j], s0, s1);
                    int ni = nq4 + 2 * p;
                    sm->Ps[hA][ni][mq4 + j]     = (s0 - bj) * sm->mss[ni] * inv_sqrt_ck;
                    sm->Ps[hA][ni + 1][mq4 + j] = (s1 - bj) * sm->mss[ni + 1] * inv_sqrt_ck;
                }
            }
        }
        __syncthreads();

        // ---- Softmax over the 4 heads (per (n,m)) ----
        for (int idx = tid; idx < NC * M_T; idx += NTHREADS) {
            int nn = idx & 31, mm = idx >> 5;
            float s0 = sm->Ps[0][nn][mm];
            float s1 = sm->Ps[1][nn][mm];
            float s2 = sm->Ps[2][nn][mm];
            float s3 = sm->Ps[3][nn][mm];
            float mx = fmaxf(fmaxf(s0, s1), fmaxf(s2, s3));
            float e0 = __expf(s0 - mx);
            float e1 = __expf(s1 - mx);
            float e2 = __expf(s2 - mx);
            float e3 = __expf(s3 - mx);
            float inv = __fdividef(1.0f, e0 + e1 + e2 + e3);
            sm->Ps[0][nn][mm] = e0 * inv;
            sm->Ps[1][nn][mm] = e1 * inv;
            sm->Ps[2][nn][mm] = e2 * inv;
            sm->Ps[3][nn][mm] = e3 * inv;
        }
        __syncthreads();

        // ---- Phase B: readout GEMM, FFMA2 with cv-pair lanes ----
        #pragma unroll 2
        for (int nn = 0; nn < NC; nn++) {
            u64 pvb[8];
            #pragma unroll
            for (int jm = 0; jm < 8; jm++) {
                float p = sm->Ps[hB][nn][mg + 8 * jm];
                pvb[jm] = pk2(p, p);
            }
            #pragma unroll
            for (int jcp = 0; jcp < 4; jcp++) {
                float2 mvf = *reinterpret_cast<const float2*>(&sm->mvs[nn][cvg * 8 + 2 * jcp]);
                u64 mv2 = pk2(mvf.x, mvf.y);
                #pragma unroll
                for (int jm = 0; jm < 8; jm++)
                    fma2(acc2[jcp][jm], mv2, pvb[jm]);
            }
        }
        __syncthreads();
    }

    // ---- Write partial sums (unpack cv pairs) ----
    float* pp = g_partial + ((size_t)(split * BSZ + b) * CVTOT) * MTOT;
    #pragma unroll
    for (int jcp = 0; jcp < 4; jcp++) {
        int cv = cvg * 8 + 2 * jcp;
        #pragma unroll
        for (int jm = 0; jm < 8; jm++) {
            float lo, hi;
            up2(acc2[jcp][jm], lo, hi);
            pp[(size_t)cv * MTOT + m0 + mg + 8 * jm]       = lo;
            pp[(size_t)(cv + 1) * MTOT + m0 + mg + 8 * jm] = hi;
        }
    }
}

// Reduce the 4 n-split partials into out[:, 0:512, :, :] and copy qv into
// out[:, 512:1024, :, :]. Vectorized float4.
__global__ void assemble_kernel(const float* __restrict__ qv, float* __restrict__ out)
{
    const int total4 = BSZ * 2 * CVTOT * MTOT / 4;  // 524288
    int idx = blockIdx.x * blockDim.x + threadIdx.x;
    if (idx >= total4) return;
    int gf  = idx * 4;
    int b   = gf >> 20;                  // 1024*1024 floats per batch
    int rem = gf & ((1 << 20) - 1);
    int ch  = rem >> 10;
    int m   = rem & 1023;

    float4 r;
    if (ch < CVTOT) {
        const size_t stride = (size_t)BSZ * CVTOT * MTOT;
        size_t off = ((size_t)b * CVTOT + ch) * MTOT + m;
        float4 a0 = *reinterpret_cast<const float4*>(g_partial + 0 * stride + off);
        float4 a1 = *reinterpret_cast<const float4*>(g_partial + 1 * stride + off);
        float4 a2 = *reinterpret_cast<const float4*>(g_partial + 2 * stride + off);
        float4 a3 = *reinterpret_cast<const float4*>(g_partial + 3 * stride + off);
        r.x = a0.x + a1.x + a2.x + a3.x;
        r.y = a0.y + a1.y + a2.y + a3.y;
        r.z = a0.z + a1.z + a2.z + a3.z;
        r.w = a0.w + a1.w + a2.w + a3.w;
    } else {
        r = *reinterpret_cast<const float4*>(
                qv + ((size_t)b * CVTOT + (ch - CVTOT)) * MTOT + m);
    }
    *reinterpret_cast<float4*>(out + (size_t)gf) = r;
}

extern "C" void kernel_launch(void* const* d_in, const int* in_sizes, int n_in,
                              void* d_out, int out_size)
{
    const float* mk = (const float*)d_in[0];
    const float* qk = (const float*)d_in[1];
    const float* ms = (const float*)d_in[2];
    const float* qe = (const float*)d_in[3];
    const float* mv = (const float*)d_in[4];
    const float* qv = (const float*)d_in[5];
    float* out = (float*)d_out;

    cudaFuncSetAttribute(mem_reader_kernel,
                         cudaFuncAttributeMaxDynamicSharedMemorySize,
                         (int)sizeof(SmemLayout));

    mem_reader_kernel<<<BSZ * 16 * NSPLIT, NTHREADS, sizeof(SmemLayout)>>>(
        mk, qk, ms, qe, mv);

    const int total4 = BSZ * 2 * CVTOT * MTOT / 4;
    assemble_kernel<<<(total4 + 255) / 256, 256>>>(qv, out);
}

// round 5
// speedup vs baseline: 1.8629x; 1.8629x over previous
#include <cuda_runtime.h>
#include <cstdint>

// ---------------- problem constants ----------------
#define HEADS_N 4
#define BSZ 2
#define NTOT 8192        // THW
#define MTOT 1024        // HW
#define CVTOT 512
#define M_T 64           // m-tile per block
#define NSPLIT 4
#define NPS (NTOT / NSPLIT)     // 2048
#define NCH 64                  // n per chunk
#define NCHUNKS (NPS / NCH)     // 32
#define NTHREADS 512

// ---------------- device scratch (no cudaMalloc allowed) ----------------
__device__ __align__(16) float g_partial[NSPLIT * BSZ * CVTOT * MTOT]; // 16 MB
__device__ __align__(16) float g_Kt[BSZ * HEADS_N * NTOT * 32];        // [b][h][n][32k perm] 8 MB
__device__ __align__(16) float g_Q [BSZ * HEADS_N * MTOT * 32];        // [b][h][m][32k perm] 1 MB
__device__ __align__(16) float g_bias[BSZ * HEADS_N * MTOT];           // 32 KB

// ---------------- smem layout (float offsets) ----------------
// bias[4][64] @0 ; msP[64] @256 ; Q[4][64][36] @384 ; Kt[4][64][36] @9600 ;
// SP[4][64][68] @18816 ; mvS[128][68] @36224 ; total 44928 floats = 179712 B
#define F_BIAS 0
#define F_MS   256
#define F_Q    384
#define F_KT   9600
#define F_SP   18816
#define F_MV   36224
#define SM_TOTAL (44928 * 4)

// ---------------- helpers ----------------
__device__ __host__ __forceinline__ int permk(int k) {
    // within-8 order [0,4,1,5,2,6,3,7]: pos = 2*(k%4) + (k%8)/4
    return (k & ~7) | ((k & 3) << 1) | ((k & 7) >> 2);
}
__device__ __forceinline__ float rn_tf32(float x) {
    uint32_t u;
    asm("cvt.rna.tf32.f32 %0, %1;" : "=r"(u) : "f"(x));
    return __uint_as_float(u);
}
__device__ __forceinline__ void mma_tf32(float* d, float2 aa, float2 ab, float2 bb) {
    // fragment: a0=(rowg,k=t) a1=(rowg+8,k=t) a2=(rowg,k=t+4) a3=(rowg+8,k=t+4)
    asm volatile(
        "mma.sync.aligned.m16n8k8.row.col.f32.tf32.tf32.f32 "
        "{%0,%1,%2,%3},{%4,%5,%6,%7},{%8,%9},{%0,%1,%2,%3};"
        : "+f"(d[0]), "+f"(d[1]), "+f"(d[2]), "+f"(d[3])
        : "r"(__float_as_uint(aa.x)), "r"(__float_as_uint(ab.x)),
          "r"(__float_as_uint(aa.y)), "r"(__float_as_uint(ab.y)),
          "r"(__float_as_uint(bb.x)), "r"(__float_as_uint(bb.y)));
}

// ---------------- precompute kernels ----------------
__global__ void prep_kt(const float* __restrict__ mk) {
    int i = blockIdx.x * blockDim.x + threadIdx.x;      // over BSZ*64*NTOT
    if (i >= BSZ * 64 * NTOT) return;
    int n  = i & (NTOT - 1);
    int ck = (i >> 13) & 63;
    int b  = i >> 19;
    float v = mk[i];
    int h = ck >> 4, c = ck & 15;
    size_t base = ((size_t)(b * HEADS_N + h) * NTOT + n) * 32;
    g_Kt[base + permk(c)]      = rn_tf32(v * v * v);
    g_Kt[base + permk(16 + c)] = rn_tf32(v);
}

__global__ void prep_q(const float* __restrict__ qk, const float* __restrict__ qe) {
    int i = blockIdx.x * blockDim.x + threadIdx.x;      // over BSZ*4*MTOT
    if (i >= BSZ * HEADS_N * MTOT) return;
    int m = i & (MTOT - 1);
    int h = (i >> 10) & 3;
    int b = i >> 12;
    size_t qb = (size_t)i * 32;
    float bias = 0.0f;
    #pragma unroll
    for (int c = 0; c < 16; c++) {
        size_t gi = ((size_t)(b * 64 + h * 16 + c)) * MTOT + m;
        float e = qe[gi];
        float k = qk[gi];
        g_Q[qb + permk(c)]      = rn_tf32(-e);
        g_Q[qb + permk(16 + c)] = rn_tf32(2.0f * k * e);
        bias += e * k * k * k;
    }
    g_bias[i] = bias;
}

// ---------------- main fused kernel ----------------
__global__ void __launch_bounds__(NTHREADS, 1)
mr_main(const float* __restrict__ mv, const float* __restrict__ ms)
{
    extern __shared__ float sm[];
    const int tid  = threadIdx.x;
    const int w    = tid >> 5;
    const int lane = tid & 31;
    const int gid  = lane >> 2;      // 0..7
    const int tig  = lane & 3;       // 0..3

    const int bx    = blockIdx.x;    // 128 blocks
    const int split = bx & 3;
    const int mtile = (bx >> 2) & 15;
    const int b     = bx >> 6;
    const int m0    = mtile * M_T;
    const int nbase = split * NPS;

    // ---- stage bias + Q (block-constant) ----
    if (tid < 256)
        sm[F_BIAS + tid] = g_bias[(size_t)(b * HEADS_N + (tid >> 6)) * MTOT + m0 + (tid & 63)];
    {
        const float4* src = (const float4*)(g_Q + (size_t)(b * HEADS_N) * MTOT * 32);
        #pragma unroll
        for (int it = 0; it < 4; it++) {
            int j = tid + it * NTHREADS;         // 2048 float4
            int kq = j & 7, mm = (j >> 3) & 63, h = j >> 9;
            float4 v = src[((size_t)h * MTOT + m0 + mm) * 8 + kq];
            *(float4*)(sm + F_Q + (h * 64 + mm) * 36 + kq * 4) = v;
        }
    }

    // Phase A mapping
    const int hA  = w >> 2;
    const int n0w = (w & 3) * 16;
    // Phase B mapping
    const int cv0   = (w & 7) * 16;
    const int mhalf = (w >> 3) * 32;

    float acc[4][4][4];   // [h][mt][reg]
    #pragma unroll
    for (int h = 0; h < 4; h++)
        #pragma unroll
        for (int mt = 0; mt < 4; mt++)
            #pragma unroll
            for (int r = 0; r < 4; r++) acc[h][mt][r] = 0.0f;

    __syncthreads();

    for (int chunk = 0; chunk < NCHUNKS; chunk++) {
        const int n0 = nbase + chunk * NCH;

        // ---- stage Kt chunk [4h][64n][36] ----
        {
            const float4* src = (const float4*)(g_Kt + (size_t)(b * HEADS_N) * NTOT * 32);
            #pragma unroll
            for (int it = 0; it < 4; it++) {
                int j = tid + it * NTHREADS;     // 2048 float4
                int kq = j & 7, nn = (j >> 3) & 63, h = j >> 9;
                float4 v = src[((size_t)h * NTOT + n0 + nn) * 8 + kq];
                *(float4*)(sm + F_KT + (h * 64 + nn) * 36 + kq * 4) = v;
            }
        }
        if (tid < 64) {
            // ms staged at permuted position so softmax reads linearly
            sm[F_MS + permk(tid)] = ms[(size_t)b * NTOT + n0 + tid];
        }
        __syncthreads();

        // ---- Phase A: S[n][m] per head, 2 passes of 4 m-tiles ----
        {
            const float* ktb = sm + F_KT + hA * 64 * 36;
            const float* qb  = sm + F_Q  + hA * 64 * 36;
            const int pos0 = n0w + ((gid & 3) << 1) + (gid >> 2);
            const int pos1 = pos0 + 8;
            #pragma unroll
            for (int pass = 0; pass < 2; pass++) {
                float sacc[4][4];
                #pragma unroll
                for (int mt = 0; mt < 4; mt++)
                    #pragma unroll
                    for (int r = 0; r < 4; r++) sacc[mt][r] = 0.0f;
                #pragma unroll
                for (int ks = 0; ks < 4; ks++) {
                    float2 aa = *(const float2*)(ktb + (n0w + gid) * 36 + ks * 8 + 2 * tig);
                    float2 ab = *(const float2*)(ktb + (n0w + gid + 8) * 36 + ks * 8 + 2 * tig);
                    #pragma unroll
                    for (int mt = 0; mt < 4; mt++) {
                        int m = (pass * 4 + mt) * 8 + gid;
                        float2 bb = *(const float2*)(qb + m * 36 + ks * 8 + 2 * tig);
                        mma_tf32(sacc[mt], aa, ab, bb);
                    }
                }
                #pragma unroll
                for (int mt = 0; mt < 4; mt++) {
                    int mcol = (pass * 4 + mt) * 8 + 2 * tig;
                    float* sp = sm + F_SP + (hA * 64 + mcol) * 68;
                    sp[pos0]      = sacc[mt][0];
                    sp[68 + pos0] = sacc[mt][1];
                    sp[pos1]      = sacc[mt][2];
                    sp[68 + pos1] = sacc[mt][3];
                }
            }
        }
        __syncthreads();

        // ---- softmax over heads, in place, write tf32 probs ----
        #pragma unroll
        for (int it = 0; it < 2; it++) {
            int i = tid + it * NTHREADS;         // 1024 groups: [64m][16 pos4]
            int m = i >> 4, p4 = i & 15;
            float4 v0 = *(float4*)(sm + F_SP + ((0 * 64 + m) * 68) + p4 * 4);
            float4 v1 = *(float4*)(sm + F_SP + ((1 * 64 + m) * 68) + p4 * 4);
            float4 v2 = *(float4*)(sm + F_SP + ((2 * 64 + m) * 68) + p4 * 4);
            float4 v3 = *(float4*)(sm + F_SP + ((3 * 64 + m) * 68) + p4 * 4);
            float4 mv4 = *(float4*)(sm + F_MS + p4 * 4);
            float b0 = sm[F_BIAS + 0 * 64 + m];
            float b1 = sm[F_BIAS + 1 * 64 + m];
            float b2 = sm[F_BIAS + 2 * 64 + m];
            float b3 = sm[F_BIAS + 3 * 64 + m];
            #pragma unroll
            for (int c = 0; c < 4; c++) {
                float msv = (&mv4.x)[c];
                float s0 = ((&v0.x)[c] - b0) * msv * 0.125f;
                float s1 = ((&v1.x)[c] - b1) * msv * 0.125f;
                float s2 = ((&v2.x)[c] - b2) * msv * 0.125f;
                float s3 = ((&v3.x)[c] - b3) * msv * 0.125f;
                float mx = fmaxf(fmaxf(s0, s1), fmaxf(s2, s3));
                float e0 = __expf(s0 - mx), e1 = __expf(s1 - mx);
                float e2 = __expf(s2 - mx), e3 = __expf(s3 - mx);
                float inv = __fdividef(1.0f, e0 + e1 + e2 + e3);
                (&v0.x)[c] = rn_tf32(e0 * inv);
                (&v1.x)[c] = rn_tf32(e1 * inv);
                (&v2.x)[c] = rn_tf32(e2 * inv);
                (&v3.x)[c] = rn_tf32(e3 * inv);
            }
            *(float4*)(sm + F_SP + ((0 * 64 + m) * 68) + p4 * 4) = v0;
            *(float4*)(sm + F_SP + ((1 * 64 + m) * 68) + p4 * 4) = v1;
            *(float4*)(sm + F_SP + ((2 * 64 + m) * 68) + p4 * 4) = v2;
            *(float4*)(sm + F_SP + ((3 * 64 + m) * 68) + p4 * 4) = v3;
        }
        __syncthreads();

        // ---- Phase B: per head, stage mv then accumulate O ----
        for (int h = 0; h < HEADS_N; h++) {
            // stage mv head tile [128cv][64n perm], tf32-rounded, pair STS.64
            const float* srcb = mv + ((size_t)(b * CVTOT + h * 128)) * NTOT + n0;
            #pragma unroll
            for (int it = 0; it < 8; it++) {
                int j = tid + it * NTHREADS;     // 4096 pairs
                int q = j & 3, g = (j >> 2) & 7, cv = j >> 5;
                const float* s = srcb + (size_t)cv * NTOT + g * 8 + q;
                float2 v;
                v.x = rn_tf32(s[0]);
                v.y = rn_tf32(s[4]);
                *(float2*)(sm + F_MV + cv * 68 + g * 8 + 2 * q) = v;
            }
            __syncthreads();

            const float* spb = sm + F_SP + h * 64 * 68;
            #pragma unroll
            for (int ks = 0; ks < 8; ks++) {
                float2 aa = *(const float2*)(sm + F_MV + (cv0 + gid) * 68 + ks * 8 + 2 * tig);
                float2 ab = *(const float2*)(sm + F_MV + (cv0 + gid + 8) * 68 + ks * 8 + 2 * tig);
                #pragma unroll
                for (int mt = 0; mt < 4; mt++) {
                    int m = mhalf + mt * 8 + gid;
                    float2 bb = *(const float2*)(spb + m * 68 + ks * 8 + 2 * tig);
                    mma_tf32(acc[h][mt], aa, ab, bb);
                }
            }
            __syncthreads();
        }
    }

    // ---- writeout: fragment-direct STG.64 into g_partial ----
    {
        float* ppb = g_partial + ((size_t)(split * BSZ + b) * CVTOT) * MTOT + m0;
        #pragma unroll
        for (int h = 0; h < 4; h++) {
            float* pp = ppb + (size_t)(h * 128) * MTOT;
            #pragma unroll
            for (int mt = 0; mt < 4; mt++) {
                int mloc = mhalf + mt * 8 + 2 * tig;
                float2 lo = { acc[h][mt][0], acc[h][mt][1] };
                float2 hi = { acc[h][mt][2], acc[h][mt][3] };
                *(float2*)(pp + (size_t)(cv0 + gid) * MTOT + mloc)     = lo;
                *(float2*)(pp + (size_t)(cv0 + gid + 8) * MTOT + mloc) = hi;
            }
        }
    }
}

// ---------------- assemble: reduce splits + copy qv ----------------
__global__ void assemble_kernel(const float* __restrict__ qv, float* __restrict__ out)
{
    const int total4 = BSZ * 2 * CVTOT * MTOT / 4;
    int idx = blockIdx.x * blockDim.x + threadIdx.x;
    if (idx >= total4) return;
    int gf  = idx * 4;
    int b   = gf >> 20;
    int rem = gf & ((1 << 20) - 1);
    int ch  = rem >> 10;
    int m   = rem & 1023;

    float4 r;
    if (ch < CVTOT) {
        const size_t stride = (size_t)BSZ * CVTOT * MTOT;
        size_t off = ((size_t)b * CVTOT + ch) * MTOT + m;
        float4 a0 = *reinterpret_cast<const float4*>(g_partial + 0 * stride + off);
        float4 a1 = *reinterpret_cast<const float4*>(g_partial + 1 * stride + off);
        float4 a2 = *reinterpret_cast<const float4*>(g_partial + 2 * stride + off);
        float4 a3 = *reinterpret_cast<const float4*>(g_partial + 3 * stride + off);
        r.x = a0.x + a1.x + a2.x + a3.x;
        r.y = a0.y + a1.y + a2.y + a3.y;
        r.z = a0.z + a1.z + a2.z + a3.z;
        r.w = a0.w + a1.w + a2.w + a3.w;
    } else {
        r = *reinterpret_cast<const float4*>(
                qv + ((size_t)b * CVTOT + (ch - CVTOT)) * MTOT + m);
    }
    *reinterpret_cast<float4*>(out + (size_t)gf) = r;
}

extern "C" void kernel_launch(void* const* d_in, const int* in_sizes, int n_in,
                              void* d_out, int out_size)
{
    const float* mk = (const float*)d_in[0];
    const float* qk = (const float*)d_in[1];
    const float* ms = (const float*)d_in[2];
    const float* qe = (const float*)d_in[3];
    const float* mv = (const float*)d_in[4];
    const float* qv = (const float*)d_in[5];
    float* out = (float*)d_out;

    prep_kt<<<(BSZ * 64 * NTOT + 255) / 256, 256>>>(mk);
    prep_q<<<(BSZ * HEADS_N * MTOT + 255) / 256, 256>>>(qk, qe);

    cudaFuncSetAttribute(mr_main, cudaFuncAttributeMaxDynamicSharedMemorySize,
                         SM_TOTAL);
    mr_main<<<BSZ * 16 * NSPLIT, NTHREADS, SM_TOTAL>>>(mv, ms);

    const int total4 = BSZ * 2 * CVTOT * MTOT / 4;
    assemble_kernel<<<(total4 + 255) / 256, 256>>>(qv, out);
}